// round 12
// baseline (speedup 1.0000x reference)
#include <cuda_runtime.h>
#include <cuda_fp16.h>
#include <cstdint>

// Problem shape (fixed by the dataset)
#define NB_ 8
#define T_  200
#define U_  50
#define J_  512
#define V_  500
#define NT_ (NB_*T_)   // 1600
#define NU_ (NB_*U_)   // 400
// rows of the big GEMM: NT_*U_ = 80000 = 625 * 128

// Scratch
__device__ float g_encP[NT_*J_];     // [1600][512] projected enc (+bias)
__device__ float g_decP[NU_*J_];     // [400][512]  projected dec (+bias)
// W_out pre-packed to fp16 fragment order:
//   [vt(2)][natom(32)][ks(32)][lane(32)] uint2
//   lane: g=lane>>2 (n within atom), t=lane&3 (k-pair)
//   .x = {W[v][k+2t], W[v][k+2t+1]}  .y = {W[v][k+2t+8], W[v][k+2t+9]}
//   v = vt*256 + natom*8 + g, k = ks*16
__device__ uint2 g_Bh[2*32*32*32];   // 512 KB

__device__ __forceinline__ uint32_t smem_u32(const void* p) {
    uint32_t a;
    asm("{ .reg .u64 t; cvta.to.shared.u64 t, %1; cvt.u32.u64 %0, t; }"
        : "=r"(a) : "l"(p));
    return a;
}
__device__ __forceinline__ float atanh_(float x) {
    float y;
    asm("tanh.approx.f32 %0, %1;" : "=f"(y) : "f"(x));
    return y;
}
__device__ __forceinline__ uint32_t h2u(float lo, float hi) {
    __half2 h = __floats2half2_rn(lo, hi);   // .x = lo, .y = hi
    return *(uint32_t*)&h;
}

// ---------------------------------------------------------------------------
// W_out -> fp16 fragment-packed gmem (one tiny launch, 0.5 MB out)
// ---------------------------------------------------------------------------
__global__ __launch_bounds__(256) void pack_w(const float* __restrict__ W)
{
    const int idx  = blockIdx.x * 256 + threadIdx.x;   // 65536 total
    const int lane = idx & 31;
    const int ks   = (idx >> 5) & 31;
    const int na   = (idx >> 10) & 31;
    const int vt   = idx >> 15;
    const int g = lane >> 2, t = lane & 3;
    const int v = vt * 256 + na * 8 + g;
    const int k = ks * 16 + 2 * t;
    float w0 = 0.f, w1 = 0.f, w2 = 0.f, w3 = 0.f;
    if (v < V_) {
        const float* r = W + (size_t)v * J_;
        w0 = r[k]; w1 = r[k+1]; w2 = r[k+8]; w3 = r[k+9];
    }
    uint2 o;
    o.x = h2u(w0, w1);
    o.y = h2u(w2, w3);
    g_Bh[idx] = o;
}

// ---------------------------------------------------------------------------
// Merged projection GEMM: C = A * W^T + bias, K = N = 512 (enc and dec)
// ---------------------------------------------------------------------------
__global__ __launch_bounds__(256) void proj_both(
    const float* __restrict__ enc, const float* __restrict__ Wenc,
    const float* __restrict__ benc, float* __restrict__ encP,
    const float* __restrict__ dec, const float* __restrict__ Wdec,
    const float* __restrict__ bdec, float* __restrict__ decP)
{
    __shared__ __align__(16) float As[64][17];
    __shared__ __align__(16) float Ws[64][17];

    const float *A, *W, *bias; float* C; int M, m0;
    if (blockIdx.y < 25) { A = enc; W = Wenc; bias = benc; C = encP; M = NT_; m0 = blockIdx.y * 64; }
    else                 { A = dec; W = Wdec; bias = bdec; C = decP; M = NU_; m0 = (blockIdx.y - 25) * 64; }

    const int tid = threadIdx.x;
    const int tx  = tid & 15;
    const int ty  = tid >> 4;
    const int j0  = blockIdx.x * 64;
    const int lr  = tid >> 2;
    const int lk  = (tid & 3) * 4;

    float acc[4][4];
#pragma unroll
    for (int i = 0; i < 4; i++)
#pragma unroll
        for (int j = 0; j < 4; j++) acc[i][j] = 0.f;

    for (int k0 = 0; k0 < 512; k0 += 16) {
        float4 av = make_float4(0.f, 0.f, 0.f, 0.f);
        if (m0 + lr < M)
            av = *(const float4*)(A + (size_t)(m0 + lr) * 512 + k0 + lk);
        float4 wv = *(const float4*)(W + (size_t)(j0 + lr) * 512 + k0 + lk);

        __syncthreads();
        As[lr][lk+0] = av.x; As[lr][lk+1] = av.y; As[lr][lk+2] = av.z; As[lr][lk+3] = av.w;
        Ws[lr][lk+0] = wv.x; Ws[lr][lk+1] = wv.y; Ws[lr][lk+2] = wv.z; Ws[lr][lk+3] = wv.w;
        __syncthreads();

#pragma unroll
        for (int k = 0; k < 16; k++) {
            float a[4], b[4];
#pragma unroll
            for (int i = 0; i < 4; i++) a[i] = As[ty + 16*i][k];
#pragma unroll
            for (int j = 0; j < 4; j++) b[j] = Ws[tx + 16*j][k];
#pragma unroll
            for (int i = 0; i < 4; i++)
#pragma unroll
                for (int j = 0; j < 4; j++)
                    acc[i][j] = fmaf(a[i], b[j], acc[i][j]);
        }
    }

#pragma unroll
    for (int i = 0; i < 4; i++) {
        int m = m0 + ty + 16*i;
        if (m >= M) continue;
#pragma unroll
        for (int j = 0; j < 4; j++) {
            int jj = j0 + tx + 16*j;
            C[(size_t)m * 512 + jj] = acc[i][j] + bias[jj];
        }
    }
}

// ---------------------------------------------------------------------------
// Main fused kernel, fp16 m16n8k16 mma.sync:
//   out[row][v] = sum_k tanh(encP[..][k] + decP[..][k]) * Wout[v][k] + bout[v]
//
// CTA tile 128 rows x 256 vocab, BK=32 (2 ksteps of 16), grid (2, 625).
// 8 warps: warpM=wid&1 (64 rows) x warpN=wid>>1 (64 cols) = 4x8 atoms, acc 128.
//
// Smem (static, 48KB exactly, double-buffered):
//   A_s[2][matom 8][ksl 2][lane 32] uint4  (8KB/buf)
//     lane (g=l>>2,t=l&3): {h2(act[16m+g][kb+2t..]), h2(act[16m+8+g][..]),
//                           h2(act[16m+g][kb+2t+8..]), h2(act[16m+8+g][..])}
//   B_s[2][natom 32][ksl 2][lane 32] uint2 (16KB/buf) -- copied via cp.async
//     straight from the pre-packed g_Bh (fragment order already).
// ---------------------------------------------------------------------------
__global__ __launch_bounds__(256, 1) void joiner_hmma(
    const float* __restrict__ bout,   // [500]
    float* __restrict__ out)          // [80000][500]
{
    __shared__ __align__(16) uint32_t A_s[2 * 2048];   // 16 KB
    __shared__ __align__(16) uint32_t B_s[2 * 4096];   // 32 KB

    const int tid  = threadIdx.x;
    const int wid  = tid >> 5;
    const int lane = tid & 31;
    const long r0  = (long)blockIdx.y * 128;
    const int vt   = blockIdx.x;               // 0..1
    const int v0   = vt * 256;
    const int warpM = wid & 1;
    const int warpN = wid >> 1;

    // ---- A staging identity: matom = wid, g = (tid>>2)&7, t = tid&3 ----
    const int sa_m = tid >> 5;
    const int sa_g = (tid >> 2) & 7;
    const int sa_t = tid & 3;
    const long rowA0 = r0 + sa_m * 16 + sa_g;
    const long rowA1 = rowA0 + 8;
    const int nt0 = (int)(rowA0 / U_);
    const int u0  = (int)(rowA0 - (long)nt0 * U_);
    const int nt1 = (int)(rowA1 / U_);
    const int u1  = (int)(rowA1 - (long)nt1 * U_);
    const float* encR0 = g_encP + (size_t)nt0 * J_;
    const float* decR0 = g_decP + ((size_t)(nt0 / T_) * U_ + u0) * J_;
    const float* encR1 = g_encP + (size_t)nt1 * J_;
    const float* decR1 = g_decP + ((size_t)(nt1 / T_) * U_ + u1) * J_;
    // A_s u32 index for (ksl): ((sa_m*2+ksl)*32 + lane)*4, lane = tid&31
    const int a_idx0 = ((sa_m * 2 + 0) * 32 + (tid & 31)) * 4;

    // ---- B cp.async identity ----
    const int b_lp  = tid & 15;          // lane-pair (16B = 2 lanes)
    const int b_ksl = (tid >> 4) & 1;
    const int b_na0 = tid >> 5;          // + 8*q, q=0..3
    const char* bh_base = (const char*)g_Bh;
    const uint32_t smemB = smem_u32(B_s);

    float acc[4][8][4];
#pragma unroll
    for (int i = 0; i < 4; i++)
#pragma unroll
        for (int j = 0; j < 8; j++)
#pragma unroll
            for (int c = 0; c < 4; c++) acc[i][j][c] = 0.f;

    // ---- B async copy: chunk kc -> buffer buf ----
    auto copyB = [&](int kc, int buf) {
#pragma unroll
        for (int q = 0; q < 4; q++) {
            const int na = b_na0 + 8 * q;
            const long goff = (long)((vt * 32 + na) * 32 + 2 * kc + b_ksl) * 256
                              + b_lp * 16;
            const uint32_t soff = (uint32_t)buf * 16384u
                                  + (uint32_t)((na * 2 + b_ksl) * 256 + b_lp * 16);
            asm volatile("cp.async.cg.shared.global [%0], [%1], 16;"
                         :: "r"(smemB + soff), "l"(bh_base + goff));
        }
        asm volatile("cp.async.commit_group;" ::: "memory");
    };
    // ---- A load (gmem -> regs) for chunk kc ----
    float2 e0[2][2], e1[2][2], d0[2][2], d1[2][2];  // [ksl][lo/hi-8]
    auto loadA = [&](int kc) {
#pragma unroll
        for (int ksl = 0; ksl < 2; ksl++) {
            const int kb = kc * 32 + ksl * 16 + 2 * sa_t;
            e0[ksl][0] = *(const float2*)(encR0 + kb);
            e0[ksl][1] = *(const float2*)(encR0 + kb + 8);
            e1[ksl][0] = *(const float2*)(encR1 + kb);
            e1[ksl][1] = *(const float2*)(encR1 + kb + 8);
            d0[ksl][0] = *(const float2*)(decR0 + kb);
            d0[ksl][1] = *(const float2*)(decR0 + kb + 8);
            d1[ksl][0] = *(const float2*)(decR1 + kb);
            d1[ksl][1] = *(const float2*)(decR1 + kb + 8);
        }
    };
    // ---- A math + store (regs -> smem buf) ----
    auto mathA = [&](int buf) {
        uint32_t* base = A_s + buf * 2048 + a_idx0;
#pragma unroll
        for (int ksl = 0; ksl < 2; ksl++) {
            uint4 w4;
            w4.x = h2u(atanh_(e0[ksl][0].x + d0[ksl][0].x),
                       atanh_(e0[ksl][0].y + d0[ksl][0].y));
            w4.y = h2u(atanh_(e1[ksl][0].x + d1[ksl][0].x),
                       atanh_(e1[ksl][0].y + d1[ksl][0].y));
            w4.z = h2u(atanh_(e0[ksl][1].x + d0[ksl][1].x),
                       atanh_(e0[ksl][1].y + d0[ksl][1].y));
            w4.w = h2u(atanh_(e1[ksl][1].x + d1[ksl][1].x),
                       atanh_(e1[ksl][1].y + d1[ksl][1].y));
            *(uint4*)(base + ksl * 128) = w4;      // (+1 ksl) -> +32 lanes*4 u32
        }
    };

    // -------- prologue: chunk 0 into buffer 0 --------
    copyB(0, 0);
    loadA(0);
    mathA(0);
    asm volatile("cp.async.wait_group 0;" ::: "memory");
    __syncthreads();

    // -------- main loop: 16 chunks, double-buffered --------
#pragma unroll 1
    for (int kc = 0; kc < 16; kc++) {
        const int cur = kc & 1;

        if (kc < 15) {
            copyB(kc + 1, 1 - cur);    // async, in flight under consume
            loadA(kc + 1);             // LDGs issued, consumed after the MMAs
        }

        // consume current buffer: 2 ksteps of m16n8k16
        const uint32_t* Ab = A_s + cur * 2048;
        const uint32_t* Bb = B_s + cur * 4096;
#pragma unroll
        for (int ksl = 0; ksl < 2; ksl++) {
            uint32_t af[4][4];
            uint32_t bf[8][2];
#pragma unroll
            for (int i = 0; i < 4; i++) {
                const uint4 va = *(const uint4*)
                    (Ab + (((warpM * 4 + i) * 2 + ksl) * 32 + lane) * 4);
                af[i][0] = va.x; af[i][1] = va.y; af[i][2] = va.z; af[i][3] = va.w;
            }
#pragma unroll
            for (int j = 0; j < 8; j++) {
                const uint2 vb = *(const uint2*)
                    (Bb + (((warpN * 8 + j) * 2 + ksl) * 32 + lane) * 2);
                bf[j][0] = vb.x; bf[j][1] = vb.y;
            }
#pragma unroll
            for (int i = 0; i < 4; i++)
#pragma unroll
                for (int j = 0; j < 8; j++) {
                    asm volatile(
                        "mma.sync.aligned.m16n8k16.row.col.f32.f16.f16.f32 "
                        "{%0,%1,%2,%3}, {%4,%5,%6,%7}, {%8,%9}, {%0,%1,%2,%3};"
                        : "+f"(acc[i][j][0]), "+f"(acc[i][j][1]),
                          "+f"(acc[i][j][2]), "+f"(acc[i][j][3])
                        : "r"(af[i][0]), "r"(af[i][1]), "r"(af[i][2]), "r"(af[i][3]),
                          "r"(bf[j][0]), "r"(bf[j][1]));
                }
        }

        if (kc < 15) mathA(1 - cur);   // tanh + pack + STS for next chunk
        asm volatile("cp.async.wait_group 0;" ::: "memory");
        __syncthreads();
    }

    // -------- epilogue: registers -> gmem, +bias, float2 stores --------
    const int cpair = (lane & 3) * 2;
    const int rsub  = lane >> 2;
#pragma unroll
    for (int j = 0; j < 8; j++) {
        const int col = v0 + warpN * 64 + j * 8 + cpair;
        if (col >= V_) continue;                  // V_ even: pair never straddles
        const float2 bb = *(const float2*)(bout + col);
#pragma unroll
        for (int i = 0; i < 4; i++) {
            const long rr = r0 + warpM * 64 + i * 16 + rsub;
            float2 o0, o1;
            o0.x = acc[i][j][0] + bb.x;
            o0.y = acc[i][j][1] + bb.y;
            o1.x = acc[i][j][2] + bb.x;
            o1.y = acc[i][j][3] + bb.y;
            *(float2*)(out + rr * (long)V_ + col)       = o0;
            *(float2*)(out + (rr + 8) * (long)V_ + col) = o1;
        }
    }
}

// ---------------------------------------------------------------------------
extern "C" void kernel_launch(void* const* d_in, const int* in_sizes, int n_in,
                              void* d_out, int out_size)
{
    (void)in_sizes; (void)n_in; (void)out_size;
    const float* encoder_out = (const float*)d_in[0];  // [8,200,512]
    const float* decoder_out = (const float*)d_in[1];  // [8,50,512]
    const float* W_enc       = (const float*)d_in[2];  // [512,512]
    const float* b_enc       = (const float*)d_in[3];  // [512]
    const float* W_dec       = (const float*)d_in[4];  // [512,512]
    const float* b_dec       = (const float*)d_in[5];  // [512]
    const float* W_out       = (const float*)d_in[6];  // [500,512]
    const float* b_out       = (const float*)d_in[7];  // [500]
    float* out = (float*)d_out;                        // [8,200,50,500]

    float* encP = nullptr;
    float* decP = nullptr;
    cudaGetSymbolAddress((void**)&encP, g_encP);
    cudaGetSymbolAddress((void**)&decP, g_decP);

    // pack W_out to fp16 fragment order (independent of projections)
    pack_w<<<256, 256>>>(W_out);

    // merged projections (enc: 25 y-tiles, dec: 7 y-tiles)
    {
        dim3 grid(8, 32);
        proj_both<<<grid, 256>>>(encoder_out, W_enc, b_enc, encP,
                                 decoder_out, W_dec, b_dec, decP);
    }
    // main fused tanh + fp16 mma.sync GEMM
    {
        dim3 grid(2, 625);   // N-tiles x M-tiles
        joiner_hmma<<<grid, 256>>>(b_out, out);
    }
}

// round 13
// speedup vs baseline: 1.0354x; 1.0354x over previous
#include <cuda_runtime.h>
#include <cuda_fp16.h>
#include <cstdint>

// Problem shape (fixed by the dataset)
#define NB_ 8
#define T_  200
#define U_  50
#define J_  512
#define V_  500
#define NT_ (NB_*T_)   // 1600
#define NU_ (NB_*U_)   // 400
// rows of the big GEMM: NT_*U_ = 80000 = 625 * 128

// Scratch
__device__ float g_encP[NT_*J_];     // [1600][512] projected enc (+bias)
__device__ float g_decP[NU_*J_];     // [400][512]  projected dec (+bias)
// W_out pre-packed to fp16 fragment order:
//   [vt(2)][natom(32)][ks(32)][lane(32)] uint2
//   lane: g=lane>>2, t=lane&3
//   .x = {W[v][k+2t], W[v][k+2t+1]}  .y = {W[v][k+2t+8], W[v][k+2t+9]}
//   v = vt*256 + natom*8 + g, k = ks*16
__device__ __align__(16) uint2 g_Bh[2*32*32*32];     // 512 KB
// Activations tanh(encP+decP) pre-packed to fp16 A-fragment order:
//   [mtile(625)][matom(8)][ks(32)][lane(32)] uint4
//   lane (g,t): .x = h2(act[r0+16ma+g][16ks+2t], +1)   .y = same, row+8
//               .z = h2(act[r0+16ma+g][16ks+2t+8], +1) .w = same, row+8
__device__ __align__(16) uint4 g_Ah[625*8*32*32];    // 82 MB

__device__ __forceinline__ uint32_t smem_u32(const void* p) {
    uint32_t a;
    asm("{ .reg .u64 t; cvta.to.shared.u64 t, %1; cvt.u32.u64 %0, t; }"
        : "=r"(a) : "l"(p));
    return a;
}
__device__ __forceinline__ float atanh_(float x) {
    float y;
    asm("tanh.approx.f32 %0, %1;" : "=f"(y) : "f"(x));
    return y;
}
__device__ __forceinline__ uint32_t h2u(float lo, float hi) {
    __half2 h = __floats2half2_rn(lo, hi);
    return *(uint32_t*)&h;
}

// ---------------------------------------------------------------------------
// W_out -> fp16 fragment-packed gmem
// ---------------------------------------------------------------------------
__global__ __launch_bounds__(256) void pack_w(const float* __restrict__ W)
{
    const int idx  = blockIdx.x * 256 + threadIdx.x;   // 65536 total
    const int lane = idx & 31;
    const int ks   = (idx >> 5) & 31;
    const int na   = (idx >> 10) & 31;
    const int vt   = idx >> 15;
    const int g = lane >> 2, t = lane & 3;
    const int v = vt * 256 + na * 8 + g;
    const int k = ks * 16 + 2 * t;
    float w0 = 0.f, w1 = 0.f, w2 = 0.f, w3 = 0.f;
    if (v < V_) {
        const float* r = W + (size_t)v * J_;
        w0 = r[k]; w1 = r[k+1]; w2 = r[k+8]; w3 = r[k+9];
    }
    uint2 o;
    o.x = h2u(w0, w1);
    o.y = h2u(w2, w3);
    g_Bh[idx] = o;
}

// ---------------------------------------------------------------------------
// Activation kernel: act = fp16(tanh(encP+decP)), written in fragment order.
// One thread = one uint4 (2 rows x 4 cols). 5.12M threads, 20000 blocks.
// ---------------------------------------------------------------------------
__global__ __launch_bounds__(256) void act_kernel()
{
    const int idx  = blockIdx.x * 256 + threadIdx.x;   // 5,120,000
    const int lane = idx & 31;
    const int ks   = (idx >> 5) & 31;
    const int ma   = (idx >> 10) & 7;
    const int mt   = idx >> 13;                        // 0..624
    const int g = lane >> 2, t = lane & 3;

    const int row0 = mt * 128 + ma * 16 + g;
    const int row1 = row0 + 8;
    const int nt0 = row0 / U_;
    const int u0  = row0 - nt0 * U_;
    const int nt1 = row1 / U_;
    const int u1  = row1 - nt1 * U_;
    const float* encR0 = g_encP + (size_t)nt0 * J_;
    const float* decR0 = g_decP + ((size_t)(nt0 / T_) * U_ + u0) * J_;
    const float* encR1 = g_encP + (size_t)nt1 * J_;
    const float* decR1 = g_decP + ((size_t)(nt1 / T_) * U_ + u1) * J_;

    const int kb = ks * 16 + 2 * t;
    float2 e0a = *(const float2*)(encR0 + kb);
    float2 d0a = *(const float2*)(decR0 + kb);
    float2 e0b = *(const float2*)(encR0 + kb + 8);
    float2 d0b = *(const float2*)(decR0 + kb + 8);
    float2 e1a = *(const float2*)(encR1 + kb);
    float2 d1a = *(const float2*)(decR1 + kb);
    float2 e1b = *(const float2*)(encR1 + kb + 8);
    float2 d1b = *(const float2*)(decR1 + kb + 8);

    uint4 o;
    o.x = h2u(atanh_(e0a.x + d0a.x), atanh_(e0a.y + d0a.y));
    o.y = h2u(atanh_(e1a.x + d1a.x), atanh_(e1a.y + d1a.y));
    o.z = h2u(atanh_(e0b.x + d0b.x), atanh_(e0b.y + d0b.y));
    o.w = h2u(atanh_(e1b.x + d1b.x), atanh_(e1b.y + d1b.y));
    g_Ah[idx] = o;
}

// ---------------------------------------------------------------------------
// Merged projection GEMM: C = A * W^T + bias, K = N = 512 (enc and dec)
// ---------------------------------------------------------------------------
__global__ __launch_bounds__(256) void proj_both(
    const float* __restrict__ enc, const float* __restrict__ Wenc,
    const float* __restrict__ benc, float* __restrict__ encP,
    const float* __restrict__ dec, const float* __restrict__ Wdec,
    const float* __restrict__ bdec, float* __restrict__ decP)
{
    __shared__ __align__(16) float As[64][17];
    __shared__ __align__(16) float Ws[64][17];

    const float *A, *W, *bias; float* C; int M, m0;
    if (blockIdx.y < 25) { A = enc; W = Wenc; bias = benc; C = encP; M = NT_; m0 = blockIdx.y * 64; }
    else                 { A = dec; W = Wdec; bias = bdec; C = decP; M = NU_; m0 = (blockIdx.y - 25) * 64; }

    const int tid = threadIdx.x;
    const int tx  = tid & 15;
    const int ty  = tid >> 4;
    const int j0  = blockIdx.x * 64;
    const int lr  = tid >> 2;
    const int lk  = (tid & 3) * 4;

    float acc[4][4];
#pragma unroll
    for (int i = 0; i < 4; i++)
#pragma unroll
        for (int j = 0; j < 4; j++) acc[i][j] = 0.f;

    for (int k0 = 0; k0 < 512; k0 += 16) {
        float4 av = make_float4(0.f, 0.f, 0.f, 0.f);
        if (m0 + lr < M)
            av = *(const float4*)(A + (size_t)(m0 + lr) * 512 + k0 + lk);
        float4 wv = *(const float4*)(W + (size_t)(j0 + lr) * 512 + k0 + lk);

        __syncthreads();
        As[lr][lk+0] = av.x; As[lr][lk+1] = av.y; As[lr][lk+2] = av.z; As[lr][lk+3] = av.w;
        Ws[lr][lk+0] = wv.x; Ws[lr][lk+1] = wv.y; Ws[lr][lk+2] = wv.z; Ws[lr][lk+3] = wv.w;
        __syncthreads();

#pragma unroll
        for (int k = 0; k < 16; k++) {
            float a[4], b[4];
#pragma unroll
            for (int i = 0; i < 4; i++) a[i] = As[ty + 16*i][k];
#pragma unroll
            for (int j = 0; j < 4; j++) b[j] = Ws[tx + 16*j][k];
#pragma unroll
            for (int i = 0; i < 4; i++)
#pragma unroll
                for (int j = 0; j < 4; j++)
                    acc[i][j] = fmaf(a[i], b[j], acc[i][j]);
        }
    }

#pragma unroll
    for (int i = 0; i < 4; i++) {
        int m = m0 + ty + 16*i;
        if (m >= M) continue;
#pragma unroll
        for (int j = 0; j < 4; j++) {
            int jj = j0 + tx + 16*j;
            C[(size_t)m * 512 + jj] = acc[i][j] + bias[jj];
        }
    }
}

// ---------------------------------------------------------------------------
// Main kernel: PURE fp16 GEMM. A and B both pre-packed in gmem, staged via
// cp.async into a 3-stage pipeline. CTA tile 128x256, BK=32, grid (2, 625).
// 8 warps: warpM=wid&1 (64 rows) x warpN=wid>>1 (64 cols) = 4x8 atoms.
// Smem: 3 stages x (A 8KB + B 16KB) = 72KB dynamic.
// ---------------------------------------------------------------------------
#define STAGE_U32 6144        // 24KB per stage in u32
#define SMEM_BYTES (3 * 24576)

__global__ __launch_bounds__(256, 1) void joiner_hmma(
    const float* __restrict__ bout,   // [500]
    float* __restrict__ out)          // [80000][500]
{
    extern __shared__ __align__(16) uint32_t smem[];

    const int tid  = threadIdx.x;
    const int wid  = tid >> 5;
    const int lane = tid & 31;
    const int mt   = blockIdx.y;               // 0..624
    const long r0  = (long)mt * 128;
    const int vt   = blockIdx.x;               // 0..1
    const int v0   = vt * 256;
    const int warpM = wid & 1;
    const int warpN = wid >> 1;

    const uint32_t smemA = smem_u32(smem);             // stage st: +st*24576
    const uint32_t smemB = smemA + 8192;               // within stage

    // ---- A cp.async identity: thread = (ma, lane); 2 copies (ksl 0,1) ----
    const int a_ma = tid >> 5;
    const char* ah_base = (const char*)g_Ah + (long)mt * 8192 * 16;
    // ---- B cp.async identity ----
    const int b_lp  = tid & 15;
    const int b_ksl = (tid >> 4) & 1;
    const int b_na0 = tid >> 5;
    const char* bh_base = (const char*)g_Bh;

    auto copyAB = [&](int kc, int st) {
        const uint32_t sb = (uint32_t)st * 24576u;
        // A: 8 matoms x 2 ksl x 32 lanes x 16B
#pragma unroll
        for (int ksl = 0; ksl < 2; ksl++) {
            const long goff = (long)((a_ma * 32 + 2 * kc + ksl) * 32 + lane) * 16;
            const uint32_t soff = sb + (uint32_t)(((a_ma * 2 + ksl) * 32 + lane) * 16);
            asm volatile("cp.async.cg.shared.global [%0], [%1], 16;"
                         :: "r"(smemA + soff), "l"(ah_base + goff));
        }
        // B: 32 natoms x 2 ksl x 32 lanes x 8B (16B per thread-slot)
#pragma unroll
        for (int q = 0; q < 4; q++) {
            const int na = b_na0 + 8 * q;
            const long goff = (long)((vt * 32 + na) * 32 + 2 * kc + b_ksl) * 256
                              + b_lp * 16;
            const uint32_t soff = sb + (uint32_t)((na * 2 + b_ksl) * 256 + b_lp * 16);
            asm volatile("cp.async.cg.shared.global [%0], [%1], 16;"
                         :: "r"(smemB + soff), "l"(bh_base + goff));
        }
        asm volatile("cp.async.commit_group;" ::: "memory");
    };

    float acc[4][8][4];
#pragma unroll
    for (int i = 0; i < 4; i++)
#pragma unroll
        for (int j = 0; j < 8; j++)
#pragma unroll
            for (int c = 0; c < 4; c++) acc[i][j][c] = 0.f;

    // -------- prologue: prefetch chunks 0 and 1 --------
    copyAB(0, 0);
    copyAB(1, 1);

    // -------- main loop: 16 chunks, 3-stage pipeline --------
#pragma unroll 1
    for (int kc = 0; kc < 16; kc++) {
        if (kc < 14)
            asm volatile("cp.async.wait_group 1;" ::: "memory");
        else
            asm volatile("cp.async.wait_group 0;" ::: "memory");
        __syncthreads();

        if (kc < 14) copyAB(kc + 2, (kc + 2) % 3);

        // consume stage kc%3: 2 ksteps of m16n8k16
        const uint32_t st = (uint32_t)(kc % 3) * 6144u;
        const uint32_t* Ab = smem + st;
        const uint32_t* Bb = smem + st + 2048;
#pragma unroll
        for (int ksl = 0; ksl < 2; ksl++) {
            uint32_t af[4][4];
            uint32_t bf[8][2];
#pragma unroll
            for (int i = 0; i < 4; i++) {
                const uint4 va = *(const uint4*)
                    (Ab + (((warpM * 4 + i) * 2 + ksl) * 32 + lane) * 4);
                af[i][0] = va.x; af[i][1] = va.y; af[i][2] = va.z; af[i][3] = va.w;
            }
#pragma unroll
            for (int j = 0; j < 8; j++) {
                const uint2 vb = *(const uint2*)
                    (Bb + (((warpN * 8 + j) * 2 + ksl) * 32 + lane) * 2);
                bf[j][0] = vb.x; bf[j][1] = vb.y;
            }
#pragma unroll
            for (int i = 0; i < 4; i++)
#pragma unroll
                for (int j = 0; j < 8; j++) {
                    asm volatile(
                        "mma.sync.aligned.m16n8k16.row.col.f32.f16.f16.f32 "
                        "{%0,%1,%2,%3}, {%4,%5,%6,%7}, {%8,%9}, {%0,%1,%2,%3};"
                        : "+f"(acc[i][j][0]), "+f"(acc[i][j][1]),
                          "+f"(acc[i][j][2]), "+f"(acc[i][j][3])
                        : "r"(af[i][0]), "r"(af[i][1]), "r"(af[i][2]), "r"(af[i][3]),
                          "r"(bf[j][0]), "r"(bf[j][1]));
                }
        }
    }

    // -------- epilogue: registers -> gmem, +bias, float2 stores --------
    const int cpair = (lane & 3) * 2;
    const int rsub  = lane >> 2;
#pragma unroll
    for (int j = 0; j < 8; j++) {
        const int col = v0 + warpN * 64 + j * 8 + cpair;
        if (col >= V_) continue;                  // V_ even: pair never straddles
        const float2 bb = *(const float2*)(bout + col);
#pragma unroll
        for (int i = 0; i < 4; i++) {
            const long rr = r0 + warpM * 64 + i * 16 + rsub;
            float2 o0, o1;
            o0.x = acc[i][j][0] + bb.x;
            o0.y = acc[i][j][1] + bb.y;
            o1.x = acc[i][j][2] + bb.x;
            o1.y = acc[i][j][3] + bb.y;
            *(float2*)(out + rr * (long)V_ + col)       = o0;
            *(float2*)(out + (rr + 8) * (long)V_ + col) = o1;
        }
    }
}

// ---------------------------------------------------------------------------
extern "C" void kernel_launch(void* const* d_in, const int* in_sizes, int n_in,
                              void* d_out, int out_size)
{
    (void)in_sizes; (void)n_in; (void)out_size;
    const float* encoder_out = (const float*)d_in[0];  // [8,200,512]
    const float* decoder_out = (const float*)d_in[1];  // [8,50,512]
    const float* W_enc       = (const float*)d_in[2];  // [512,512]
    const float* b_enc       = (const float*)d_in[3];  // [512]
    const float* W_dec       = (const float*)d_in[4];  // [512,512]
    const float* b_dec       = (const float*)d_in[5];  // [512]
    const float* W_out       = (const float*)d_in[6];  // [500,512]
    const float* b_out       = (const float*)d_in[7];  // [500]
    float* out = (float*)d_out;                        // [8,200,50,500]

    float* encP = nullptr;
    float* decP = nullptr;
    cudaGetSymbolAddress((void**)&encP, g_encP);
    cudaGetSymbolAddress((void**)&decP, g_decP);

    cudaFuncSetAttribute(joiner_hmma,
                         cudaFuncAttributeMaxDynamicSharedMemorySize, SMEM_BYTES);

    // pack W_out to fp16 fragment order (independent of projections)
    pack_w<<<256, 256>>>(W_out);

    // merged projections (enc: 25 y-tiles, dec: 7 y-tiles)
    {
        dim3 grid(8, 32);
        proj_both<<<grid, 256>>>(encoder_out, W_enc, b_enc, encP,
                                 decoder_out, W_dec, b_dec, decP);
    }
    // activations: tanh(encP+decP) -> fp16 fragment-packed gmem
    act_kernel<<<20000, 256>>>();

    // main pure fp16 GEMM
    {
        dim3 grid(2, 625);   // N-tiles x M-tiles
        joiner_hmma<<<grid, 256, SMEM_BYTES>>>(b_out, out);
    }
}

// round 14
// speedup vs baseline: 1.2740x; 1.2305x over previous
#include <cuda_runtime.h>
#include <cuda_fp16.h>
#include <cstdint>

// Problem shape (fixed by the dataset)
#define NB_ 8
#define T_  200
#define U_  50
#define J_  512
#define V_  500
#define NT_ (NB_*T_)   // 1600
#define NU_ (NB_*U_)   // 400
// rows of the big GEMM: NT_*U_ = 80000 = 625 * 128

// Scratch
__device__ float g_encP[NT_*J_];     // [1600][512] projected enc (+bias)
__device__ float g_decP[NU_*J_];     // [400][512]  projected dec (+bias)
// W_out pre-packed to fp16 fragment order:
//   [globalNa(64)][ks(32)][lane(32)] uint2   (globalNa = v/8)
//   lane: g=lane>>2, t=lane&3
//   .x = {W[v][k+2t], W[v][k+2t+1]}  .y = {W[v][k+2t+8], W[v][k+2t+9]}
//   v = globalNa*8 + g, k = ks*16
__device__ __align__(16) uint2 g_Bh[64*32*32];       // 512 KB
// Activations tanh(encP+decP) pre-packed to fp16 A-fragment order:
//   [mtile(625)][matom(8)][ks(32)][lane(32)] uint4
__device__ __align__(16) uint4 g_Ah[625*8*32*32];    // 82 MB

__device__ __forceinline__ uint32_t smem_u32(const void* p) {
    uint32_t a;
    asm("{ .reg .u64 t; cvta.to.shared.u64 t, %1; cvt.u32.u64 %0, t; }"
        : "=r"(a) : "l"(p));
    return a;
}
__device__ __forceinline__ float atanh_(float x) {
    float y;
    asm("tanh.approx.f32 %0, %1;" : "=f"(y) : "f"(x));
    return y;
}
__device__ __forceinline__ uint32_t h2u(float lo, float hi) {
    __half2 h = __floats2half2_rn(lo, hi);
    return *(uint32_t*)&h;
}
// split a float pair into fp16 hi + fp16 residual lo (packed half2 words)
__device__ __forceinline__ void split2(float a, float b, uint32_t& hi, uint32_t& lo) {
    __half ha = __float2half_rn(a), hb = __float2half_rn(b);
    float ra = a - __half2float(ha), rb = b - __half2float(hb);
    __half2 h = __halves2half2(ha, hb);
    __half2 l = __floats2half2_rn(ra, rb);
    hi = *(uint32_t*)&h;
    lo = *(uint32_t*)&l;
}

#define HMMA16816(ac, a0,a1,a2,a3, b0,b1)                                      \
    asm volatile(                                                              \
        "mma.sync.aligned.m16n8k16.row.col.f32.f16.f16.f32 "                   \
        "{%0,%1,%2,%3}, {%4,%5,%6,%7}, {%8,%9}, {%0,%1,%2,%3};"                \
        : "+f"((ac)[0]), "+f"((ac)[1]), "+f"((ac)[2]), "+f"((ac)[3])           \
        : "r"(a0), "r"(a1), "r"(a2), "r"(a3), "r"(b0), "r"(b1))

// ---------------------------------------------------------------------------
// W_out -> fp16 fragment-packed gmem
// ---------------------------------------------------------------------------
__global__ __launch_bounds__(256) void pack_w(const float* __restrict__ W)
{
    const int idx  = blockIdx.x * 256 + threadIdx.x;   // 65536 total
    const int lane = idx & 31;
    const int ks   = (idx >> 5) & 31;
    const int gna  = idx >> 10;                         // 0..63
    const int g = lane >> 2, t = lane & 3;
    const int v = gna * 8 + g;
    const int k = ks * 16 + 2 * t;
    float w0 = 0.f, w1 = 0.f, w2 = 0.f, w3 = 0.f;
    if (v < V_) {
        const float* r = W + (size_t)v * J_;
        w0 = r[k]; w1 = r[k+1]; w2 = r[k+8]; w3 = r[k+9];
    }
    uint2 o;
    o.x = h2u(w0, w1);
    o.y = h2u(w2, w3);
    g_Bh[idx] = o;
}

// ---------------------------------------------------------------------------
// Activation kernel: act = fp16(tanh(encP+decP)), written in fragment order.
// ---------------------------------------------------------------------------
__global__ __launch_bounds__(256) void act_kernel()
{
    const int idx  = blockIdx.x * 256 + threadIdx.x;   // 5,120,000
    const int lane = idx & 31;
    const int ks   = (idx >> 5) & 31;
    const int ma   = (idx >> 10) & 7;
    const int mt   = idx >> 13;                        // 0..624
    const int g = lane >> 2, t = lane & 3;

    const int row0 = mt * 128 + ma * 16 + g;
    const int row1 = row0 + 8;
    const int nt0 = row0 / U_;
    const int u0  = row0 - nt0 * U_;
    const int nt1 = row1 / U_;
    const int u1  = row1 - nt1 * U_;
    const float* encR0 = g_encP + (size_t)nt0 * J_;
    const float* decR0 = g_decP + ((size_t)(nt0 / T_) * U_ + u0) * J_;
    const float* encR1 = g_encP + (size_t)nt1 * J_;
    const float* decR1 = g_decP + ((size_t)(nt1 / T_) * U_ + u1) * J_;

    const int kb = ks * 16 + 2 * t;
    float2 e0a = *(const float2*)(encR0 + kb);
    float2 d0a = *(const float2*)(decR0 + kb);
    float2 e0b = *(const float2*)(encR0 + kb + 8);
    float2 d0b = *(const float2*)(decR0 + kb + 8);
    float2 e1a = *(const float2*)(encR1 + kb);
    float2 d1a = *(const float2*)(decR1 + kb);
    float2 e1b = *(const float2*)(encR1 + kb + 8);
    float2 d1b = *(const float2*)(decR1 + kb + 8);

    uint4 o;
    o.x = h2u(atanh_(e0a.x + d0a.x), atanh_(e0a.y + d0a.y));
    o.y = h2u(atanh_(e1a.x + d1a.x), atanh_(e1a.y + d1a.y));
    o.z = h2u(atanh_(e0b.x + d0b.x), atanh_(e0b.y + d0b.y));
    o.w = h2u(atanh_(e1b.x + d1b.x), atanh_(e1b.y + d1b.y));
    g_Ah[idx] = o;
}

// ---------------------------------------------------------------------------
// Projection GEMM via split-fp16 HMMA (hi+lo, drop lo*lo; err ~2^-21):
//   C[m][j] = sum_k A[m][k] W[j][k] + bias[j],  K = 512
// CTA tile 64 rows x 64 cols; grid (8 jtiles, 32 mtiles: 25 enc + 7 dec).
// 8 warps: warpM=wid&3 (16 rows) x warpN=wid>>2 (32 cols = 4 natoms).
// Smem: A/B hi+lo fragment-ordered, 16 KB total, single-buffered.
// ---------------------------------------------------------------------------
__global__ __launch_bounds__(256) void proj_hmma(
    const float* __restrict__ enc, const float* __restrict__ Wenc,
    const float* __restrict__ benc, float* __restrict__ encP,
    const float* __restrict__ dec, const float* __restrict__ Wdec,
    const float* __restrict__ bdec, float* __restrict__ decP)
{
    __shared__ __align__(16) uint32_t Ah_s[1024], Al_s[1024];   // 4KB each
    __shared__ __align__(16) uint32_t Bh_s[1024], Bl_s[1024];   // 4KB each

    const float *A, *W, *bias; float* C; int M, m0;
    if (blockIdx.y < 25) { A = enc; W = Wenc; bias = benc; C = encP; M = NT_; m0 = blockIdx.y * 64; }
    else                 { A = dec; W = Wdec; bias = bdec; C = decP; M = NU_; m0 = (blockIdx.y - 25) * 64; }

    const int tid  = threadIdx.x;
    const int wid  = tid >> 5;
    const int lane = tid & 31;
    const int j0   = blockIdx.x * 64;
    const int warpM = wid & 3;
    const int warpN = wid >> 2;

    // A staging (tid < 128): thread = (ma(4), g(8), t(4))
    const int sa_m = (tid >> 5) & 3;
    const int sa_t = tid & 3;
    const int sa_lane = tid & 31;                 // = g*4 + t
    const int rowA0 = m0 + sa_m * 16 + ((tid >> 2) & 7);
    const int rowA1 = rowA0 + 8;
    // B staging (tid >= 128): thread = (na(8), ksl(2), lq(8))
    const int ts    = tid & 127;
    const int sb_na = ts >> 4;
    const int sb_ksl = (ts >> 3) & 1;
    const int sb_lq = ts & 7;
    const int jW = j0 + sb_na * 8 + sb_lq;        // < 512 always

    float acc[4][4];
#pragma unroll
    for (int j = 0; j < 4; j++)
#pragma unroll
        for (int c = 0; c < 4; c++) acc[j][c] = 0.f;

#pragma unroll 1
    for (int kc = 0; kc < 16; kc++) {
        const int k0 = kc * 32;
        if (tid < 128) {
            const float* r0p = A + (size_t)rowA0 * 512;
            const float* r1p = A + (size_t)rowA1 * 512;
            const bool ok0 = rowA0 < M, ok1 = rowA1 < M;
#pragma unroll
            for (int ksl = 0; ksl < 2; ksl++) {
                const int kb = k0 + ksl * 16 + 2 * sa_t;
                float2 z = make_float2(0.f, 0.f);
                float2 x0a = ok0 ? *(const float2*)(r0p + kb)     : z;
                float2 x0b = ok0 ? *(const float2*)(r0p + kb + 8) : z;
                float2 x1a = ok1 ? *(const float2*)(r1p + kb)     : z;
                float2 x1b = ok1 ? *(const float2*)(r1p + kb + 8) : z;
                uint4 hi, lo;
                split2(x0a.x, x0a.y, hi.x, lo.x);
                split2(x1a.x, x1a.y, hi.y, lo.y);
                split2(x0b.x, x0b.y, hi.z, lo.z);
                split2(x1b.x, x1b.y, hi.w, lo.w);
                const int idx = ((sa_m * 2 + ksl) * 32 + sa_lane) * 4;
                *(uint4*)&Ah_s[idx] = hi;
                *(uint4*)&Al_s[idx] = lo;
            }
        } else {
            const float* wr = W + (size_t)jW * 512;
            const int kb = k0 + sb_ksl * 16;
            float wv[16];
            *(float4*)&wv[0]  = *(const float4*)(wr + kb);
            *(float4*)&wv[4]  = *(const float4*)(wr + kb + 4);
            *(float4*)&wv[8]  = *(const float4*)(wr + kb + 8);
            *(float4*)&wv[12] = *(const float4*)(wr + kb + 12);
#pragma unroll
            for (int t = 0; t < 4; t++) {
                const int l = sb_lq * 4 + t;
                uint32_t hx, lx, hy, ly;
                split2(wv[2*t],     wv[2*t + 1], hx, lx);
                split2(wv[2*t + 8], wv[2*t + 9], hy, ly);
                const int idx = ((sb_na * 2 + sb_ksl) * 32 + l) * 2;
                Bh_s[idx] = hx; Bh_s[idx + 1] = hy;
                Bl_s[idx] = lx; Bl_s[idx + 1] = ly;
            }
        }
        __syncthreads();

#pragma unroll
        for (int ksl = 0; ksl < 2; ksl++) {
            const int aidx = ((warpM * 2 + ksl) * 32 + lane) * 4;
            const uint4 ah = *(const uint4*)&Ah_s[aidx];
            const uint4 al = *(const uint4*)&Al_s[aidx];
#pragma unroll
            for (int j = 0; j < 4; j++) {
                const int bidx = (((warpN * 4 + j) * 2 + ksl) * 32 + lane) * 2;
                const uint2 bh = *(const uint2*)&Bh_s[bidx];
                const uint2 bl = *(const uint2*)&Bl_s[bidx];
                HMMA16816(acc[j], ah.x, ah.y, ah.z, ah.w, bh.x, bh.y);
                HMMA16816(acc[j], ah.x, ah.y, ah.z, ah.w, bl.x, bl.y);
                HMMA16816(acc[j], al.x, al.y, al.z, al.w, bh.x, bh.y);
            }
        }
        __syncthreads();
    }

    // epilogue
    const int rsub = lane >> 2;
    const int cp   = (lane & 3) * 2;
#pragma unroll
    for (int j = 0; j < 4; j++) {
        const int col = j0 + (warpN * 4 + j) * 8 + cp;       // < 512 always
        const float2 bb = *(const float2*)(bias + col);
        const int m0r = m0 + warpM * 16 + rsub;
        if (m0r < M) {
            float2 o; o.x = acc[j][0] + bb.x; o.y = acc[j][1] + bb.y;
            *(float2*)(C + (size_t)m0r * 512 + col) = o;
        }
        if (m0r + 8 < M) {
            float2 o; o.x = acc[j][2] + bb.x; o.y = acc[j][3] + bb.y;
            *(float2*)(C + (size_t)(m0r + 8) * 512 + col) = o;
        }
    }
}

// ---------------------------------------------------------------------------
// Main kernel: pure fp16 GEMM, 128x128 CTA tile, 2 CTAs/SM.
// grid (4, 625). 8 warps: warpM=wid&3 (32 rows = 2 matoms), warpN=wid>>2
// (64 cols = 8 natoms). acc = 2x8x4 = 64 regs. BK=32 (2 ksteps of 16).
// Smem: 3 stages x (A 8KB + B 8KB) = 48KB static per CTA.
// ---------------------------------------------------------------------------
__global__ __launch_bounds__(256, 2) void joiner_hmma(
    const float* __restrict__ bout,   // [500]
    float* __restrict__ out)          // [80000][500]
{
    __shared__ __align__(16) uint32_t smem[3 * 4096];   // 48 KB

    const int tid  = threadIdx.x;
    const int wid  = tid >> 5;
    const int lane = tid & 31;
    const int mt   = blockIdx.y;               // 0..624
    const long r0  = (long)mt * 128;
    const int vt   = blockIdx.x;               // 0..3
    const int v0   = vt * 128;
    const int warpM = wid & 3;
    const int warpN = wid >> 2;

    const uint32_t smemBase = smem_u32(smem);
    const char* ah_base = (const char*)g_Ah + (long)mt * (8 * 32 * 32 * 16);
    const char* bh_base = (const char*)g_Bh;

    // per-thread copy slots (2 A-slots + 2 B-slots of 16B each per chunk)
    const int s0 = tid * 2, s1 = s0 + 1;
    const int ama0 = s0 >> 6, aksl0 = (s0 >> 5) & 1, alane0 = s0 & 31;
    const int ama1 = s1 >> 6, aksl1 = (s1 >> 5) & 1, alane1 = s1 & 31;
    const int bna0 = s0 >> 5, bksl0 = (s0 >> 4) & 1, blp0 = s0 & 15;
    const int bna1 = s1 >> 5, bksl1 = (s1 >> 4) & 1, blp1 = s1 & 15;
    const int gna0 = vt * 16 + bna0, gna1 = vt * 16 + bna1;

    auto copyAB = [&](int kc, int st) {
        const uint32_t sb = smemBase + (uint32_t)st * 16384u;
        // A: [ma(8)][ksl(2)][lane(32)] x 16B
        {
            const long  g0 = (long)((ama0 * 32 + 2 * kc + aksl0) * 32 + alane0) * 16;
            const uint32_t o0 = sb + (uint32_t)(((ama0 * 2 + aksl0) * 32 + alane0) * 16);
            asm volatile("cp.async.cg.shared.global [%0], [%1], 16;"
                         :: "r"(o0), "l"(ah_base + g0));
            const long  g1 = (long)((ama1 * 32 + 2 * kc + aksl1) * 32 + alane1) * 16;
            const uint32_t o1 = sb + (uint32_t)(((ama1 * 2 + aksl1) * 32 + alane1) * 16);
            asm volatile("cp.async.cg.shared.global [%0], [%1], 16;"
                         :: "r"(o1), "l"(ah_base + g1));
        }
        // B: [na(16)][ksl(2)] x 256B
        {
            const long  g0 = (long)((gna0 * 32 + 2 * kc + bksl0) * 256 + blp0 * 16);
            const uint32_t o0 = sb + 8192u + (uint32_t)((bna0 * 2 + bksl0) * 256 + blp0 * 16);
            asm volatile("cp.async.cg.shared.global [%0], [%1], 16;"
                         :: "r"(o0), "l"(bh_base + g0));
            const long  g1 = (long)((gna1 * 32 + 2 * kc + bksl1) * 256 + blp1 * 16);
            const uint32_t o1 = sb + 8192u + (uint32_t)((bna1 * 2 + bksl1) * 256 + blp1 * 16);
            asm volatile("cp.async.cg.shared.global [%0], [%1], 16;"
                         :: "r"(o1), "l"(bh_base + g1));
        }
        asm volatile("cp.async.commit_group;" ::: "memory");
    };

    float acc[2][8][4];
#pragma unroll
    for (int i = 0; i < 2; i++)
#pragma unroll
        for (int j = 0; j < 8; j++)
#pragma unroll
            for (int c = 0; c < 4; c++) acc[i][j][c] = 0.f;

    // prologue: prefetch chunks 0 and 1
    copyAB(0, 0);
    copyAB(1, 1);

#pragma unroll 1
    for (int kc = 0; kc < 16; kc++) {
        if (kc < 14)
            asm volatile("cp.async.wait_group 1;" ::: "memory");
        else
            asm volatile("cp.async.wait_group 0;" ::: "memory");
        __syncthreads();

        if (kc < 14) copyAB(kc + 2, (kc + 2) % 3);

        const uint32_t* Ab = smem + (kc % 3) * 4096;
        const uint32_t* Bb = Ab + 2048;
#pragma unroll
        for (int ksl = 0; ksl < 2; ksl++) {
            uint32_t af[2][4];
            uint32_t bf[8][2];
#pragma unroll
            for (int mi = 0; mi < 2; mi++) {
                const uint4 va = *(const uint4*)
                    (Ab + (((warpM * 2 + mi) * 2 + ksl) * 32 + lane) * 4);
                af[mi][0] = va.x; af[mi][1] = va.y; af[mi][2] = va.z; af[mi][3] = va.w;
            }
#pragma unroll
            for (int j = 0; j < 8; j++) {
                const uint2 vb = *(const uint2*)
                    (Bb + (((warpN * 8 + j) * 2 + ksl) * 32 + lane) * 2);
                bf[j][0] = vb.x; bf[j][1] = vb.y;
            }
#pragma unroll
            for (int mi = 0; mi < 2; mi++)
#pragma unroll
                for (int j = 0; j < 8; j++)
                    HMMA16816(acc[mi][j], af[mi][0], af[mi][1], af[mi][2], af[mi][3],
                              bf[j][0], bf[j][1]);
        }
    }

    // epilogue: registers -> gmem, +bias, float2 stores
    const int cpair = (lane & 3) * 2;
    const int rsub  = lane >> 2;
#pragma unroll
    for (int j = 0; j < 8; j++) {
        const int col = v0 + warpN * 64 + j * 8 + cpair;
        if (col >= V_) continue;                  // V_ even: pair never straddles
        const float2 bb = *(const float2*)(bout + col);
#pragma unroll
        for (int mi = 0; mi < 2; mi++) {
            const long rr = r0 + warpM * 32 + mi * 16 + rsub;
            float2 o0, o1;
            o0.x = acc[mi][j][0] + bb.x;
            o0.y = acc[mi][j][1] + bb.y;
            o1.x = acc[mi][j][2] + bb.x;
            o1.y = acc[mi][j][3] + bb.y;
            *(float2*)(out + rr * (long)V_ + col)       = o0;
            *(float2*)(out + (rr + 8) * (long)V_ + col) = o1;
        }
    }
}

// ---------------------------------------------------------------------------
extern "C" void kernel_launch(void* const* d_in, const int* in_sizes, int n_in,
                              void* d_out, int out_size)
{
    (void)in_sizes; (void)n_in; (void)out_size;
    const float* encoder_out = (const float*)d_in[0];  // [8,200,512]
    const float* decoder_out = (const float*)d_in[1];  // [8,50,512]
    const float* W_enc       = (const float*)d_in[2];  // [512,512]
    const float* b_enc       = (const float*)d_in[3];  // [512]
    const float* W_dec       = (const float*)d_in[4];  // [512,512]
    const float* b_dec       = (const float*)d_in[5];  // [512]
    const float* W_out       = (const float*)d_in[6];  // [500,512]
    const float* b_out       = (const float*)d_in[7];  // [500]
    float* out = (float*)d_out;                        // [8,200,50,500]

    float* encP = nullptr;
    float* decP = nullptr;
    cudaGetSymbolAddress((void**)&encP, g_encP);
    cudaGetSymbolAddress((void**)&decP, g_decP);

    // pack W_out to fp16 fragment order (independent of projections)
    pack_w<<<256, 256>>>(W_out);

    // projections via split-fp16 HMMA (enc: 25 mtiles, dec: 7 mtiles)
    {
        dim3 grid(8, 32);
        proj_hmma<<<grid, 256>>>(encoder_out, W_enc, b_enc, encP,
                                 decoder_out, W_dec, b_dec, decP);
    }
    // activations: tanh(encP+decP) -> fp16 fragment-packed gmem
    act_kernel<<<20000, 256>>>();

    // main pure fp16 GEMM (128x128 tiles, 2 CTAs/SM)
    {
        dim3 grid(4, 625);   // N-tiles x M-tiles
        joiner_hmma<<<grid, 256>>>(b_out, out);
    }
}